// round 12
// baseline (speedup 1.0000x reference)
#include <cuda_runtime.h>
#include <cuda_fp16.h>
#include <cstdint>
#include <cstddef>

// ============================================================================
// NF4Linear: out[8192,4096] = x[8192,4096] @ W^T[4096,4096]
//   W = dequant_nf4(indices, q_scales) -> fp16 (bit-exact vs reference cast)
//   x fp32 -> fp16 (only error source, ~2e-4 rel)
// GEMM: mma.sync m16n8k16 fp16.
// R11: 128x128 CTA tile, BK=64, 3-stage cp.async, 128 thr = 4 warps (2m x 2n,
// warp tile 64x64), 2 CTAs/SM. Combines R9's smem-traffic cut (LDSM+STS
// 192KB/SM/kt = 1536cyc < 2048cyc HMMA floor) with R10's independent-CTA
// barrier decoupling. R10 had both pipes at exactly 100% -> overlap slip.
// ============================================================================

#define OUT_F 4096
#define IN_F  4096
#define M_TOTAL 8192

#define BM 128
#define BN 128
#define BK 64
#define K_TILES (IN_F / BK)      // 64
#define STAGES 3
#define A_BYTES (BM * 128)       // 16384
#define B_BYTES (BN * 128)       // 16384
#define STAGE_BYTES (A_BYTES + B_BYTES)       // 32768
#define SMEM_DYN (STAGES * STAGE_BYTES)       // 98304 per CTA
#define NTHREADS 128

// Scratch in device globals (allocation-guard-safe per skill rules)
__device__ __half g_W[(size_t)OUT_F * IN_F];     // 32 MB
__device__ __half g_X[(size_t)M_TOTAL * IN_F];   // 64 MB

__constant__ float c_nf4[16] = {
    -1.0f, -0.6961928009986877f, -0.5250730514526367f, -0.39491748809814453f,
    -0.28444138169288635f, -0.18477343022823334f, -0.09105003625154495f, 0.0f,
    0.07958029955625534f, 0.16093020141124725f, 0.24611230194568634f,
    0.33791524171829224f, 0.44070982933044434f, 0.5626170039176941f,
    0.7229568362236023f, 1.0f};

// ---------------------------------------------------------------------------
// Helpers (arch-generic PTX only)
// ---------------------------------------------------------------------------
__device__ __forceinline__ uint32_t smem_u32(const void* p) {
    uint32_t a;
    asm("{ .reg .u64 t; cvta.to.shared.u64 t, %1; cvt.u32.u64 %0, t; }"
        : "=r"(a) : "l"(p));
    return a;
}

__device__ __forceinline__ void cp16(uint32_t s, const void* g) {
    asm volatile("cp.async.cg.shared.global [%0], [%1], 16;" :: "r"(s), "l"(g));
}

__device__ __forceinline__ void ldsm4(uint32_t* r, uint32_t addr) {
    asm volatile("ldmatrix.sync.aligned.m8n8.x4.shared.b16 {%0,%1,%2,%3}, [%4];"
                 : "=r"(r[0]), "=r"(r[1]), "=r"(r[2]), "=r"(r[3]) : "r"(addr));
}

__device__ __forceinline__ void mma16816(float* c, const uint32_t* a,
                                         const uint32_t* b) {
    asm volatile(
        "mma.sync.aligned.m16n8k16.row.col.f32.f16.f16.f32 "
        "{%0,%1,%2,%3}, {%4,%5,%6,%7}, {%8,%9}, {%0,%1,%2,%3};"
        : "+f"(c[0]), "+f"(c[1]), "+f"(c[2]), "+f"(c[3])
        : "r"(a[0]), "r"(a[1]), "r"(a[2]), "r"(a[3]), "r"(b[0]), "r"(b[1]));
}

// SW128-style swizzle for 128B rows: XOR 16B-col bits with (row&7)
__device__ __forceinline__ uint32_t swz(int row, int col16) {
    return (uint32_t)(row * 128) + (((uint32_t)col16 * 16) ^ ((uint32_t)(row & 7) << 4));
}

// ---------------------------------------------------------------------------
// Dequant: indices[16M] + q_scales[256K] -> g_W fp16 (matches ref exactly)
// ---------------------------------------------------------------------------
__global__ __launch_bounds__(256) void dequant_kernel(
    const int* __restrict__ idx, const int* __restrict__ qs) {
    __shared__ float lut[16];
    if (threadIdx.x < 16) lut[threadIdx.x] = c_nf4[threadIdx.x];
    __syncthreads();

    size_t t = (size_t)blockIdx.x * 256 + threadIdx.x;
    float absmax = ((float)qs[t >> 3] / 127.0f) * 0.05f;  // ref op order

    const int4* ip = reinterpret_cast<const int4*>(idx) + t * 2;
    int4 a = ip[0];
    int4 b = ip[1];
    __half h[8];
    h[0] = __float2half_rn(lut[a.x] * absmax);
    h[1] = __float2half_rn(lut[a.y] * absmax);
    h[2] = __float2half_rn(lut[a.z] * absmax);
    h[3] = __float2half_rn(lut[a.w] * absmax);
    h[4] = __float2half_rn(lut[b.x] * absmax);
    h[5] = __float2half_rn(lut[b.y] * absmax);
    h[6] = __float2half_rn(lut[b.z] * absmax);
    h[7] = __float2half_rn(lut[b.w] * absmax);
    reinterpret_cast<uint4*>(g_W)[t] = *reinterpret_cast<uint4*>(h);
}

// ---------------------------------------------------------------------------
// Convert x fp32 -> fp16
// ---------------------------------------------------------------------------
__global__ __launch_bounds__(256) void convert_kernel(const float* __restrict__ x) {
    size_t t = (size_t)blockIdx.x * 256 + threadIdx.x;  // 8 floats per thread
    const float4* xp = reinterpret_cast<const float4*>(x) + t * 2;
    float4 a = xp[0];
    float4 b = xp[1];
    __half h[8];
    h[0] = __float2half_rn(a.x); h[1] = __float2half_rn(a.y);
    h[2] = __float2half_rn(a.z); h[3] = __float2half_rn(a.w);
    h[4] = __float2half_rn(b.x); h[5] = __float2half_rn(b.y);
    h[6] = __float2half_rn(b.z); h[7] = __float2half_rn(b.w);
    reinterpret_cast<uint4*>(g_X)[t] = *reinterpret_cast<uint4*>(h);
}

// ---------------------------------------------------------------------------
// GEMM: D[M,N] = A[M,K] . B[N,K]^T  (A = g_X, B = g_W, both K-major fp16)
// Grid (N/128, M/128) = (32, 64). 128 threads = 4 warps (2m x 2n),
// warp tile 64x64. BK=64 (4 k16 steps per stage). 2 CTAs per SM.
// ---------------------------------------------------------------------------
__device__ __forceinline__ void load_stage(uint32_t sA, const __half* a0,
                                           const __half* b0, int tid) {
    const uint32_t sBb = sA + A_BYTES;
    #pragma unroll
    for (int i = tid; i < BM * 8; i += NTHREADS) {     // 8 iters
        const int r = i >> 3, c = i & 7;
        cp16(sA + swz(r, c), a0 + (size_t)r * IN_F + c * 8);
    }
    #pragma unroll
    for (int i = tid; i < BN * 8; i += NTHREADS) {     // 8 iters
        const int r = i >> 3, c = i & 7;
        cp16(sBb + swz(r, c), b0 + (size_t)r * IN_F + c * 8);
    }
}

__global__ __launch_bounds__(NTHREADS, 2)
void gemm_kernel(float* __restrict__ out) {
    extern __shared__ __align__(1024) char smem[];
    const uint32_t sb = smem_u32(smem);
    const int tid = threadIdx.x;
    const int lane = tid & 31;
    const int wid = tid >> 5;
    const int tn = blockIdx.x;
    const int tm = blockIdx.y;
    const int mw = wid >> 1;   // 0..1  (m position of warp, 64 rows each)
    const int nw = wid & 1;    // 0..1  (n position of warp, 64 cols each)

    const __half* gA = g_X + (size_t)tm * BM * IN_F;
    const __half* gB = g_W + (size_t)tn * BN * IN_F;

    // ldmatrix lane decomposition: tile index t4 (0..3), row-in-tile i8 (0..7)
    const int t4 = lane >> 3;
    const int i8 = lane & 7;
    // A frag (per mi 0..3): m = mw*64 + mi*16 + ((t4&1)<<3)+i8,
    //   16B-col = 2*ks + (t4>>1)
    const int rowA0 = mw * 64 + ((t4 & 1) << 3) + i8;
    // B frag (per p 0..3): n = nw*64 + p*16 + ((t4>>1)<<3)+i8,
    //   16B-col = 2*ks + (t4&1)
    const int rowB0 = nw * 64 + ((t4 >> 1) << 3) + i8;
    const int acolsel = t4 >> 1;
    const int bcolsel = t4 & 1;

    // ---------------- prologue: fill STAGES-1 = 2 pipeline stages ------------
    #pragma unroll
    for (int s = 0; s < STAGES - 1; ++s) {
        load_stage(sb + s * STAGE_BYTES, gA + s * BK, gB + s * BK, tid);
        asm volatile("cp.async.commit_group;" ::: "memory");
    }

    float acc[4][8][4];
    #pragma unroll
    for (int mi = 0; mi < 4; ++mi)
        #pragma unroll
        for (int o = 0; o < 8; ++o)
            #pragma unroll
            for (int q = 0; q < 4; ++q) acc[mi][o][q] = 0.0f;

    // ---------------- main loop ----------------
    int s_cur = 0;   // kt % 3
    int s_nxt = 2;   // (kt+2) % 3 target buffer for prefetch
    for (int kt = 0; kt < K_TILES; ++kt) {
        asm volatile("cp.async.wait_group 1;" ::: "memory");
        __syncthreads();

        // prefetch stage kt+2 into buffer (kt+2)%3 = (kt-1)%3 (freed by the
        // barrier above: all warps are past iteration kt-1's compute)
        if (kt + STAGES - 1 < K_TILES) {
            load_stage(sb + s_nxt * STAGE_BYTES,
                       gA + (kt + STAGES - 1) * BK,
                       gB + (kt + STAGES - 1) * BK, tid);
        }
        asm volatile("cp.async.commit_group;" ::: "memory");

        const uint32_t sA = sb + s_cur * STAGE_BYTES;
        const uint32_t sBb = sA + A_BYTES;

        #pragma unroll
        for (int ks = 0; ks < BK / 16; ++ks) {
            uint32_t a[4][4], b[4][4];
            #pragma unroll
            for (int mi = 0; mi < 4; ++mi)
                ldsm4(a[mi], sA + swz(rowA0 + mi * 16, 2 * ks + acolsel));
            #pragma unroll
            for (int p = 0; p < 4; ++p)
                ldsm4(b[p], sBb + swz(rowB0 + p * 16, 2 * ks + bcolsel));
            #pragma unroll
            for (int mi = 0; mi < 4; ++mi)
                #pragma unroll
                for (int p = 0; p < 4; ++p) {
                    mma16816(acc[mi][2 * p + 0], a[mi], &b[p][0]);
                    mma16816(acc[mi][2 * p + 1], a[mi], &b[p][2]);
                }
        }

        s_cur = (s_cur == 2) ? 0 : s_cur + 1;
        s_nxt = (s_nxt == 2) ? 0 : s_nxt + 1;
    }

    // ---------------- epilogue: registers -> gmem ----------------
    const int gid = lane >> 2;   // row within 8-row group
    const int tq = lane & 3;     // n pair index
    #pragma unroll
    for (int mi = 0; mi < 4; ++mi) {
        const size_t r0 = (size_t)(tm * BM + mw * 64 + mi * 16 + gid);
        #pragma unroll
        for (int oct = 0; oct < 8; ++oct) {
            const size_t n = (size_t)(tn * BN + nw * 64 + oct * 8 + 2 * tq);
            float2 v0 = make_float2(acc[mi][oct][0], acc[mi][oct][1]);
            float2 v1 = make_float2(acc[mi][oct][2], acc[mi][oct][3]);
            *reinterpret_cast<float2*>(out + r0 * OUT_F + n) = v0;
            *reinterpret_cast<float2*>(out + (r0 + 8) * OUT_F + n) = v1;
        }
    }
}

// ---------------------------------------------------------------------------
// Launch
// ---------------------------------------------------------------------------
extern "C" void kernel_launch(void* const* d_in, const int* in_sizes, int n_in,
                              void* d_out, int out_size) {
    const float* x = (const float*)d_in[0];        // [4,2048,4096] fp32
    const int* indices = (const int*)d_in[1];      // [16777216] int32
    const int* q_scales = (const int*)d_in[2];     // [262144] int32
    float* out = (float*)d_out;                    // [4,2048,4096] fp32

    (void)in_sizes; (void)n_in; (void)out_size;

    dequant_kernel<<<8192, 256>>>(indices, q_scales);
    convert_kernel<<<16384, 256>>>(x);

    cudaFuncSetAttribute(gemm_kernel,
                         cudaFuncAttributeMaxDynamicSharedMemorySize, SMEM_DYN);
    dim3 grid(OUT_F / BN, M_TOTAL / BM);   // (32, 64)
    gemm_kernel<<<grid, NTHREADS, SMEM_DYN>>>(out);
}

// round 14
// speedup vs baseline: 1.0187x; 1.0187x over previous
#include <cuda_runtime.h>
#include <cuda_fp16.h>
#include <cstdint>
#include <cstddef>

// ============================================================================
// NF4Linear: out[8192,4096] = x[8192,4096] @ W^T[4096,4096]
//   W = dequant_nf4(indices, q_scales) -> fp16 (bit-exact vs reference cast)
//   x fp32 -> fp16 (only error source, ~2e-4 rel)
// GEMM = exact R10 best config (657us): mma.sync m16n8k16, 128x128 CTA tile,
// BK=64, 3-stage cp.async, 256 thr = 8 warps (4m x 2n, warp tile 32x64),
// 2 CTAs/SM.
// R13 failed on an infra flake ("container failed twice") with a known-good
// GEMM + inert prep fusion; R14 resubmits the same artifact per rigor.md
// (re-bench before concluding). Prep fusion saves a launch + tail and aligns
// ncu -s 5 -c 1 onto the GEMM (2 launches/replay: p,g,p,g,p,[g]).
// ============================================================================

#define OUT_F 4096
#define IN_F  4096
#define M_TOTAL 8192

#define BM 128
#define BN 128
#define BK 64
#define K_TILES (IN_F / BK)      // 64
#define STAGES 3
#define A_BYTES (BM * 128)       // 16384
#define B_BYTES (BN * 128)       // 16384
#define STAGE_BYTES (A_BYTES + B_BYTES)       // 32768
#define SMEM_DYN (STAGES * STAGE_BYTES)       // 98304 per CTA
#define NTHREADS 256

// Prep kernel grid split
#define DQ_BLOCKS 8192           // 8192*256 threads * 8 weights = 16M weights
#define CV_BLOCKS 16384          // 16384*256 threads * 8 floats  = 32M elems

// Scratch in device globals (allocation-guard-safe per skill rules)
__device__ __half g_W[(size_t)OUT_F * IN_F];     // 32 MB
__device__ __half g_X[(size_t)M_TOTAL * IN_F];   // 64 MB

__constant__ float c_nf4[16] = {
    -1.0f, -0.6961928009986877f, -0.5250730514526367f, -0.39491748809814453f,
    -0.28444138169288635f, -0.18477343022823334f, -0.09105003625154495f, 0.0f,
    0.07958029955625534f, 0.16093020141124725f, 0.24611230194568634f,
    0.33791524171829224f, 0.44070982933044434f, 0.5626170039176941f,
    0.7229568362236023f, 1.0f};

// ---------------------------------------------------------------------------
// Helpers (arch-generic PTX only)
// ---------------------------------------------------------------------------
__device__ __forceinline__ uint32_t smem_u32(const void* p) {
    uint32_t a;
    asm("{ .reg .u64 t; cvta.to.shared.u64 t, %1; cvt.u32.u64 %0, t; }"
        : "=r"(a) : "l"(p));
    return a;
}

__device__ __forceinline__ void cp16(uint32_t s, const void* g) {
    asm volatile("cp.async.cg.shared.global [%0], [%1], 16;" :: "r"(s), "l"(g));
}

__device__ __forceinline__ void ldsm4(uint32_t* r, uint32_t addr) {
    asm volatile("ldmatrix.sync.aligned.m8n8.x4.shared.b16 {%0,%1,%2,%3}, [%4];"
                 : "=r"(r[0]), "=r"(r[1]), "=r"(r[2]), "=r"(r[3]) : "r"(addr));
}

__device__ __forceinline__ void mma16816(float* c, const uint32_t* a,
                                         const uint32_t* b) {
    asm volatile(
        "mma.sync.aligned.m16n8k16.row.col.f32.f16.f16.f32 "
        "{%0,%1,%2,%3}, {%4,%5,%6,%7}, {%8,%9}, {%0,%1,%2,%3};"
        : "+f"(c[0]), "+f"(c[1]), "+f"(c[2]), "+f"(c[3])
        : "r"(a[0]), "r"(a[1]), "r"(a[2]), "r"(a[3]), "r"(b[0]), "r"(b[1]));
}

// SW128-style swizzle for 128B rows: XOR 16B-col bits with (row&7)
__device__ __forceinline__ uint32_t swz(int row, int col16) {
    return (uint32_t)(row * 128) + (((uint32_t)col16 * 16) ^ ((uint32_t)(row & 7) << 4));
}

// ---------------------------------------------------------------------------
// Fused prep: blocks [0, DQ_BLOCKS) dequantize W; the rest convert x.
//   dequant: matches reference fp16 cast bit-exactly (lut * absmax, rn).
//   convert: x fp32 -> fp16 rn.
// ---------------------------------------------------------------------------
__global__ __launch_bounds__(256) void prep_kernel(
    const int* __restrict__ idx, const int* __restrict__ qs,
    const float* __restrict__ x) {
    if (blockIdx.x < DQ_BLOCKS) {
        __shared__ float lut[16];
        if (threadIdx.x < 16) lut[threadIdx.x] = c_nf4[threadIdx.x];
        __syncthreads();

        size_t t = (size_t)blockIdx.x * 256 + threadIdx.x;  // 8 weights/thread
        float absmax = ((float)qs[t >> 3] / 127.0f) * 0.05f;  // ref op order

        const int4* ip = reinterpret_cast<const int4*>(idx) + t * 2;
        int4 a = ip[0];
        int4 b = ip[1];
        __half h[8];
        h[0] = __float2half_rn(lut[a.x] * absmax);
        h[1] = __float2half_rn(lut[a.y] * absmax);
        h[2] = __float2half_rn(lut[a.z] * absmax);
        h[3] = __float2half_rn(lut[a.w] * absmax);
        h[4] = __float2half_rn(lut[b.x] * absmax);
        h[5] = __float2half_rn(lut[b.y] * absmax);
        h[6] = __float2half_rn(lut[b.z] * absmax);
        h[7] = __float2half_rn(lut[b.w] * absmax);
        reinterpret_cast<uint4*>(g_W)[t] = *reinterpret_cast<uint4*>(h);
    } else {
        size_t t = (size_t)(blockIdx.x - DQ_BLOCKS) * 256 + threadIdx.x;
        const float4* xp = reinterpret_cast<const float4*>(x) + t * 2;
        float4 a = xp[0];
        float4 b = xp[1];
        __half h[8];
        h[0] = __float2half_rn(a.x); h[1] = __float2half_rn(a.y);
        h[2] = __float2half_rn(a.z); h[3] = __float2half_rn(a.w);
        h[4] = __float2half_rn(b.x); h[5] = __float2half_rn(b.y);
        h[6] = __float2half_rn(b.z); h[7] = __float2half_rn(b.w);
        reinterpret_cast<uint4*>(g_X)[t] = *reinterpret_cast<uint4*>(h);
    }
}

// ---------------------------------------------------------------------------
// GEMM: D[M,N] = A[M,K] . B[N,K]^T  (A = g_X, B = g_W, both K-major fp16)
// Grid (N/128, M/128) = (32, 64). 256 threads = 8 warps (4m x 2n),
// warp tile 32x64. BK=64 (4 k16 steps per stage). 2 CTAs per SM.
// (Exact R10 configuration -- best measured: 657us.)
// ---------------------------------------------------------------------------
__device__ __forceinline__ void load_stage(uint32_t sA, const __half* a0,
                                           const __half* b0, int tid) {
    const uint32_t sBb = sA + A_BYTES;
    #pragma unroll
    for (int i = tid; i < BM * 8; i += NTHREADS) {     // 4 iters
        const int r = i >> 3, c = i & 7;
        cp16(sA + swz(r, c), a0 + (size_t)r * IN_F + c * 8);
    }
    #pragma unroll
    for (int i = tid; i < BN * 8; i += NTHREADS) {     // 4 iters
        const int r = i >> 3, c = i & 7;
        cp16(sBb + swz(r, c), b0 + (size_t)r * IN_F + c * 8);
    }
}

__global__ __launch_bounds__(NTHREADS, 2)
void gemm_kernel(float* __restrict__ out) {
    extern __shared__ __align__(1024) char smem[];
    const uint32_t sb = smem_u32(smem);
    const int tid = threadIdx.x;
    const int lane = tid & 31;
    const int wid = tid >> 5;
    const int tn = blockIdx.x;
    const int tm = blockIdx.y;
    const int mw = wid >> 1;   // 0..3  (m position of warp, 32 rows each)
    const int nw = wid & 1;    // 0..1  (n position of warp, 64 cols each)

    const __half* gA = g_X + (size_t)tm * BM * IN_F;
    const __half* gB = g_W + (size_t)tn * BN * IN_F;

    // ldmatrix lane decomposition: tile index t4 (0..3), row-in-tile i8 (0..7)
    const int t4 = lane >> 3;
    const int i8 = lane & 7;
    // A frag (per mi 0..1): m = mw*32 + mi*16 + ((t4&1)<<3)+i8,
    //   16B-col = 2*ks + (t4>>1)
    const int rowA0 = mw * 32 + ((t4 & 1) << 3) + i8;
    // B frag (per p 0..3): n = nw*64 + p*16 + ((t4>>1)<<3)+i8,
    //   16B-col = 2*ks + (t4&1)
    const int rowB0 = nw * 64 + ((t4 >> 1) << 3) + i8;
    const int acolsel = t4 >> 1;
    const int bcolsel = t4 & 1;

    // ---------------- prologue: fill STAGES-1 = 2 pipeline stages ------------
    #pragma unroll
    for (int s = 0; s < STAGES - 1; ++s) {
        load_stage(sb + s * STAGE_BYTES, gA + s * BK, gB + s * BK, tid);
        asm volatile("cp.async.commit_group;" ::: "memory");
    }

    float acc[2][8][4];
    #pragma unroll
    for (int mi = 0; mi < 2; ++mi)
        #pragma unroll
        for (int o = 0; o < 8; ++o)
            #pragma unroll
            for (int q = 0; q < 4; ++q) acc[mi][o][q] = 0.0f;

    // ---------------- main loop ----------------
    int s_cur = 0;   // kt % 3
    int s_nxt = 2;   // (kt+2) % 3 target buffer for prefetch
    for (int kt = 0; kt < K_TILES; ++kt) {
        asm volatile("cp.async.wait_group 1;" ::: "memory");
        __syncthreads();

        // prefetch stage kt+2 into buffer (kt+2)%3 = (kt-1)%3 (freed by the
        // barrier above: all warps are past iteration kt-1's compute)
        if (kt + STAGES - 1 < K_TILES) {
            load_stage(sb + s_nxt * STAGE_BYTES,
                       gA + (kt + STAGES - 1) * BK,
                       gB + (kt + STAGES - 1) * BK, tid);
        }
        asm volatile("cp.async.commit_group;" ::: "memory");

        const uint32_t sA = sb + s_cur * STAGE_BYTES;
        const uint32_t sBb = sA + A_BYTES;

        #pragma unroll
        for (int ks = 0; ks < BK / 16; ++ks) {
            uint32_t a[2][4], b[4][4];
            ldsm4(a[0], sA + swz(rowA0, 2 * ks + acolsel));
            ldsm4(a[1], sA + swz(rowA0 + 16, 2 * ks + acolsel));
            #pragma unroll
            for (int p = 0; p < 4; ++p)
                ldsm4(b[p], sBb + swz(rowB0 + p * 16, 2 * ks + bcolsel));
            #pragma unroll
            for (int mi = 0; mi < 2; ++mi)
                #pragma unroll
                for (int p = 0; p < 4; ++p) {
                    mma16816(acc[mi][2 * p + 0], a[mi], &b[p][0]);
                    mma16816(acc[mi][2 * p + 1], a[mi], &b[p][2]);
                }
        }

        s_cur = (s_cur == 2) ? 0 : s_cur + 1;
        s_nxt = (s_nxt == 2) ? 0 : s_nxt + 1;
    }

    // ---------------- epilogue: registers -> gmem ----------------
    const int gid = lane >> 2;   // row within 8-row group
    const int tq = lane & 3;     // n pair index
    #pragma unroll
    for (int mi = 0; mi < 2; ++mi) {
        const size_t r0 = (size_t)(tm * BM + mw * 32 + mi * 16 + gid);
        #pragma unroll
        for (int oct = 0; oct < 8; ++oct) {
            const size_t n = (size_t)(tn * BN + nw * 64 + oct * 8 + 2 * tq);
            float2 v0 = make_float2(acc[mi][oct][0], acc[mi][oct][1]);
            float2 v1 = make_float2(acc[mi][oct][2], acc[mi][oct][3]);
            *reinterpret_cast<float2*>(out + r0 * OUT_F + n) = v0;
            *reinterpret_cast<float2*>(out + (r0 + 8) * OUT_F + n) = v1;
        }
    }
}

// ---------------------------------------------------------------------------
// Launch: 2 kernels per call (prep fused) so ncu -s 5 -c 1 lands on the GEMM.
// ---------------------------------------------------------------------------
extern "C" void kernel_launch(void* const* d_in, const int* in_sizes, int n_in,
                              void* d_out, int out_size) {
    const float* x = (const float*)d_in[0];        // [4,2048,4096] fp32
    const int* indices = (const int*)d_in[1];      // [16777216] int32
    const int* q_scales = (const int*)d_in[2];     // [262144] int32
    float* out = (float*)d_out;                    // [4,2048,4096] fp32

    (void)in_sizes; (void)n_in; (void)out_size;

    prep_kernel<<<DQ_BLOCKS + CV_BLOCKS, 256>>>(indices, q_scales, x);

    cudaFuncSetAttribute(gemm_kernel,
                         cudaFuncAttributeMaxDynamicSharedMemorySize, SMEM_DYN);
    dim3 grid(OUT_F / BN, M_TOTAL / BM);   // (32, 64)
    gemm_kernel<<<grid, NTHREADS, SMEM_DYN>>>(out);
}